// round 1
// baseline (speedup 1.0000x reference)
#include <cuda_runtime.h>
#include <math.h>
#include <stdint.h>

// Problem constants
#define TT 4096      // B*S tokens
#define DD 768       // model dim
#define EE 8         // experts
#define KX 2         // top-k
#define HH 2048      // expert hidden

// ---------------- scratch (device globals; no runtime allocation) ----------------
__device__ float g_act [(size_t)EE*TT*HH];      // per-expert SwiGLU activations (E,T,H)
__device__ float g_eo  [(size_t)TT*EE*DD];      // expert outputs (T,E,D)
__device__ float g_qkv [(size_t)TT*EE*3*DD];    // qkv scratch (router 32768x2304 / collab 8192x2304)
__device__ float g_attn[(size_t)TT*EE*DD];      // attention out scratch
__device__ float g_proj[(size_t)TT*EE*DD];      // out-proj scratch
__device__ float g_ctx [(size_t)TT*EE*DD];      // router ctx after RMS
__device__ float g_rprobs[TT*EE];               // routing softmax probs
__device__ int   g_tkidx[TT*KX];
__device__ float g_tkp  [TT*KX];
__device__ float g_sf [(size_t)TT*KX*DD];       // selected experts (T*K, D)
__device__ float g_ao [(size_t)TT*KX*DD];
__device__ float g_h1 [(size_t)TT*KX*DD];
__device__ float g_ref[(size_t)TT*KX*DD];
__device__ float g_comb[(size_t)TT*DD];
__device__ float g_ent[TT];

// ---------------- generic tiled SGEMM: C = A * op(B) (+bias)(+gelu)(+resid) ----------------
// A: M x Kd row-major (lda). BT=true: B is N x Kd (use B^T). BT=false: B is Kd x N.
// Requires M%64==0, N%64==0, Kd%16==0 (all shapes here satisfy this).
template<bool BT>
__global__ void __launch_bounds__(256) gemm_kernel(
    const float* __restrict__ A, int lda, size_t sA,
    const float* __restrict__ B, int ldb, size_t sB,
    const float* __restrict__ bias,
    const float* __restrict__ resid,
    float* __restrict__ C, int ldc, size_t sC,
    int M, int N, int Kd, int epi)   // epi: 0 none, 1 exact GELU
{
    __shared__ float As[16][68];
    __shared__ float Bs[16][68];
    const int tid = threadIdx.x;
    A += sA * blockIdx.z; B += sB * blockIdx.z; C += sC * blockIdx.z;
    const int rowBase = blockIdx.y * 64;
    const int colBase = blockIdx.x * 64;
    const int am = tid >> 2, ak = (tid & 3) << 2;       // A/BT loads: 64 rows x 16 k
    const int bk = tid >> 4, bn = (tid & 15) << 2;      // NN loads: 16 k x 64 n
    const int ty = tid >> 4, tx = tid & 15;

    float acc[4][4] = {};
    for (int k0 = 0; k0 < Kd; k0 += 16) {
        float4 av = *reinterpret_cast<const float4*>(A + (size_t)(rowBase + am) * lda + k0 + ak);
        As[ak  ][am] = av.x; As[ak+1][am] = av.y; As[ak+2][am] = av.z; As[ak+3][am] = av.w;
        if (BT) {
            float4 bv = *reinterpret_cast<const float4*>(B + (size_t)(colBase + am) * ldb + k0 + ak);
            Bs[ak  ][am] = bv.x; Bs[ak+1][am] = bv.y; Bs[ak+2][am] = bv.z; Bs[ak+3][am] = bv.w;
        } else {
            float4 bv = *reinterpret_cast<const float4*>(B + (size_t)(k0 + bk) * ldb + colBase + bn);
            *reinterpret_cast<float4*>(&Bs[bk][bn]) = bv;
        }
        __syncthreads();
        #pragma unroll
        for (int kk = 0; kk < 16; kk++) {
            float4 a4 = *reinterpret_cast<const float4*>(&As[kk][ty * 4]);
            float4 b4 = *reinterpret_cast<const float4*>(&Bs[kk][tx * 4]);
            float ar[4] = {a4.x, a4.y, a4.z, a4.w};
            float br[4] = {b4.x, b4.y, b4.z, b4.w};
            #pragma unroll
            for (int i = 0; i < 4; i++)
                #pragma unroll
                for (int j = 0; j < 4; j++)
                    acc[i][j] = fmaf(ar[i], br[j], acc[i][j]);
        }
        __syncthreads();
    }
    #pragma unroll
    for (int i = 0; i < 4; i++) {
        int r = rowBase + ty * 4 + i;
        float4 o;
        float* po = &o.x;
        #pragma unroll
        for (int j = 0; j < 4; j++) {
            int c = colBase + tx * 4 + j;
            float v = acc[i][j];
            if (bias)  v += __ldg(&bias[c]);
            if (epi == 1) v = 0.5f * v * (1.0f + erff(v * 0.7071067811865475f));
            if (resid) v += resid[(size_t)r * N + c];
            po[j] = v;
        }
        *reinterpret_cast<float4*>(C + (size_t)r * ldc + colBase + tx * 4) = o;
    }
}

// ---------------- fused SwiGLU dual GEMM: act = silu(x@w1[e]) * (x@w3[e]) ----------------
__global__ void __launch_bounds__(256) swiglu_kernel(
    const float* __restrict__ X,    // T x D
    const float* __restrict__ W1,   // E x D x H
    const float* __restrict__ W3,   // E x D x H
    float* __restrict__ ACT)        // E x T x H
{
    __shared__ float As [16][68];
    __shared__ float B1s[16][68];
    __shared__ float B3s[16][68];
    const int tid = threadIdx.x;
    const int e = blockIdx.z;
    const float* Bw1 = W1 + (size_t)e * DD * HH;
    const float* Bw3 = W3 + (size_t)e * DD * HH;
    float* Cp = ACT + (size_t)e * TT * HH;
    const int rowBase = blockIdx.y * 64;
    const int colBase = blockIdx.x * 64;
    const int am = tid >> 2, ak = (tid & 3) << 2;
    const int bk = tid >> 4, bn = (tid & 15) << 2;
    const int ty = tid >> 4, tx = tid & 15;

    float ag[4][4] = {};
    float au[4][4] = {};
    for (int k0 = 0; k0 < DD; k0 += 16) {
        float4 av = *reinterpret_cast<const float4*>(X + (size_t)(rowBase + am) * DD + k0 + ak);
        As[ak  ][am] = av.x; As[ak+1][am] = av.y; As[ak+2][am] = av.z; As[ak+3][am] = av.w;
        float4 b1 = *reinterpret_cast<const float4*>(Bw1 + (size_t)(k0 + bk) * HH + colBase + bn);
        *reinterpret_cast<float4*>(&B1s[bk][bn]) = b1;
        float4 b3 = *reinterpret_cast<const float4*>(Bw3 + (size_t)(k0 + bk) * HH + colBase + bn);
        *reinterpret_cast<float4*>(&B3s[bk][bn]) = b3;
        __syncthreads();
        #pragma unroll
        for (int kk = 0; kk < 16; kk++) {
            float4 a4 = *reinterpret_cast<const float4*>(&As[kk][ty * 4]);
            float4 g4 = *reinterpret_cast<const float4*>(&B1s[kk][tx * 4]);
            float4 u4 = *reinterpret_cast<const float4*>(&B3s[kk][tx * 4]);
            float ar[4] = {a4.x, a4.y, a4.z, a4.w};
            float gr[4] = {g4.x, g4.y, g4.z, g4.w};
            float ur[4] = {u4.x, u4.y, u4.z, u4.w};
            #pragma unroll
            for (int i = 0; i < 4; i++)
                #pragma unroll
                for (int j = 0; j < 4; j++) {
                    ag[i][j] = fmaf(ar[i], gr[j], ag[i][j]);
                    au[i][j] = fmaf(ar[i], ur[j], au[i][j]);
                }
        }
        __syncthreads();
    }
    #pragma unroll
    for (int i = 0; i < 4; i++) {
        int r = rowBase + ty * 4 + i;
        float4 o;
        float* po = &o.x;
        #pragma unroll
        for (int j = 0; j < 4; j++) {
            float g = ag[i][j];
            float s = g / (1.0f + expf(-g));   // silu
            po[j] = s * au[i][j];
        }
        *reinterpret_cast<float4*>(Cp + (size_t)r * HH + colBase + tx * 4) = o;
    }
}

// ---------------- router self-attention over E=8 positions, 12 heads, hd=64 ----------------
__global__ void __launch_bounds__(96) router_attn_kernel(
    const float* __restrict__ QKV,   // (T*8) x 2304
    float* __restrict__ O)           // (T*8) x 768
{
    __shared__ float sK[8 * 768];
    __shared__ float sV[8 * 768];
    const int t = blockIdx.x;
    const int tid = threadIdx.x;
    const float* base = QKV + (size_t)t * 8 * 2304;
    for (int i = tid; i < 8 * 768; i += 96) {
        int pos = i / 768, c = i - pos * 768;
        sK[i] = base[(size_t)pos * 2304 +  768 + c];
        sV[i] = base[(size_t)pos * 2304 + 1536 + c];
    }
    __syncthreads();
    const int head = tid / 8, qi = tid % 8;   // 12 heads x 8 query positions
    const float* q = base + (size_t)qi * 2304 + head * 64;
    float s[8] = {0.f};
    for (int d = 0; d < 64; d++) {
        float qd = q[d];
        #pragma unroll
        for (int m = 0; m < 8; m++) s[m] = fmaf(qd, sK[m * 768 + head * 64 + d], s[m]);
    }
    float mx = -1e30f;
    #pragma unroll
    for (int m = 0; m < 8; m++) { s[m] *= 0.125f; mx = fmaxf(mx, s[m]); }
    float den = 0.f;
    #pragma unroll
    for (int m = 0; m < 8; m++) { s[m] = expf(s[m] - mx); den += s[m]; }
    float inv = 1.0f / den;
    #pragma unroll
    for (int m = 0; m < 8; m++) s[m] *= inv;
    float* op = O + (size_t)(t * 8 + qi) * 768 + head * 64;
    for (int d = 0; d < 64; d++) {
        float o = 0.f;
        #pragma unroll
        for (int m = 0; m < 8; m++) o = fmaf(s[m], sV[m * 768 + head * 64 + d], o);
        op[d] = o;
    }
}

// ---------------- RMS-norm with residual: O = rms(Y + R) * W  (rows x 768) ----------------
__global__ void __launch_bounds__(256) rms_kernel(
    const float* __restrict__ Y, const float* __restrict__ R,
    const float* __restrict__ W, float* __restrict__ O)
{
    const int row = blockIdx.x, tid = threadIdx.x;
    const float* y = Y + (size_t)row * 768;
    const float* r = R + (size_t)row * 768;
    float v[3]; float ss = 0.f;
    #pragma unroll
    for (int i = 0; i < 3; i++) {
        int c = tid + i * 256;
        float s = y[c] + r[c];
        v[i] = s; ss = fmaf(s, s, ss);
    }
    __shared__ float red[256];
    red[tid] = ss; __syncthreads();
    for (int o = 128; o > 0; o >>= 1) { if (tid < o) red[tid] += red[tid + o]; __syncthreads(); }
    float scale = rsqrtf(red[0] * (1.0f / 768.0f) + 1e-5f);
    #pragma unroll
    for (int i = 0; i < 3; i++) {
        int c = tid + i * 256;
        O[(size_t)row * 768 + c] = v[i] * scale * W[c];
    }
}

// ---------------- logits, routing softmax, top-2 ----------------
__global__ void __launch_bounds__(256) logits_kernel(
    const float* __restrict__ CTX,   // (T*8) x 768
    const float* __restrict__ GW,    // 8 x 768
    float* __restrict__ rprobs, int* __restrict__ tkidx,
    float* __restrict__ tkp, float* __restrict__ out_idx_f)
{
    const int t = blockIdx.x, tid = threadIdx.x;
    __shared__ float mv[768];
    const float* c0 = CTX + (size_t)t * 8 * 768;
    for (int i = tid; i < 768; i += 256) {
        float s = 0.f;
        #pragma unroll
        for (int p = 0; p < 8; p++) s += c0[p * 768 + i];
        mv[i] = s * 0.125f;
    }
    __syncthreads();
    const int w = tid >> 5, lane = tid & 31;
    float part = 0.f;
    for (int i = lane; i < 768; i += 32) part = fmaf(mv[i], GW[w * 768 + i], part);
    #pragma unroll
    for (int o = 16; o; o >>= 1) part += __shfl_xor_sync(0xffffffffu, part, o);
    __shared__ float lg[8];
    if (lane == 0) lg[w] = part;
    __syncthreads();
    if (tid == 0) {
        float mx = lg[0];
        #pragma unroll
        for (int e = 1; e < 8; e++) mx = fmaxf(mx, lg[e]);
        float ex[8], den = 0.f;
        #pragma unroll
        for (int e = 0; e < 8; e++) { ex[e] = expf(lg[e] - mx); den += ex[e]; }
        float inv = 1.0f / den;
        #pragma unroll
        for (int e = 0; e < 8; e++) rprobs[t * 8 + e] = ex[e] * inv;
        int i0 = 0;
        #pragma unroll
        for (int e = 1; e < 8; e++) if (lg[e] > lg[i0]) i0 = e;
        int i1 = -1;
        #pragma unroll
        for (int e = 0; e < 8; e++) if (e != i0 && (i1 < 0 || lg[e] > lg[i1])) i1 = e;
        tkidx[t * 2] = i0; tkidx[t * 2 + 1] = i1;
        float eb = expf(lg[i1] - lg[i0]);
        float p0 = 1.0f / (1.0f + eb);
        tkp[t * 2] = p0; tkp[t * 2 + 1] = eb * p0;
        if (out_idx_f) { out_idx_f[t * 2] = (float)i0; out_idx_f[t * 2 + 1] = (float)i1; }
    }
}

// ---------------- gather selected experts ----------------
__global__ void gather_kernel(const float* __restrict__ eo, const int* __restrict__ tkidx,
                              float* __restrict__ sf)
{
    const int total = TT * KX * DD;
    for (int idx = blockIdx.x * blockDim.x + threadIdx.x; idx < total; idx += gridDim.x * blockDim.x) {
        int d = idx % DD;
        int r = idx / DD;
        int t = r >> 1, k = r & 1;
        sf[idx] = eo[(size_t)t * EE * DD + (size_t)tkidx[t * 2 + k] * DD + d];
    }
}

// ---------------- collaborative attention: L=2, 2 heads, hd=384; also entropy ----------------
__global__ void __launch_bounds__(256) collab_attn_kernel(
    const float* __restrict__ QKV,   // (T*2) x 2304
    float* __restrict__ O,           // (T*2) x 768
    float* __restrict__ ent)         // per-token entropy sum
{
    const int t = blockIdx.x, tid = threadIdx.x;
    const float* base = QKV + (size_t)t * 2 * 2304;
    __shared__ float sc[2][2][2];  // [head][qi][kj]
    __shared__ float sp[2][2][2];  // probs
    const int w = tid >> 5, lane = tid & 31;
    {
        int h = (w >> 2) & 1, qi = (w >> 1) & 1, kj = w & 1;
        float part = 0.f;
        const float* qp = base + (size_t)qi * 2304 + h * 384;
        const float* kp = base + (size_t)kj * 2304 + 768 + h * 384;
        for (int d = lane; d < 384; d += 32) part = fmaf(qp[d], kp[d], part);
        #pragma unroll
        for (int o = 16; o; o >>= 1) part += __shfl_xor_sync(0xffffffffu, part, o);
        if (lane == 0) sc[h][qi][kj] = part * 0.05103103630798288f;  // 1/sqrt(384)
    }
    __syncthreads();
    if (tid < 4) {
        int h = tid >> 1, qi = tid & 1;
        float s0 = sc[h][qi][0], s1 = sc[h][qi][1];
        float m = fmaxf(s0, s1);
        float e0 = expf(s0 - m), e1 = expf(s1 - m);
        float inv = 1.0f / (e0 + e1);
        sp[h][qi][0] = e0 * inv; sp[h][qi][1] = e1 * inv;
    }
    __syncthreads();
    if (tid == 0) {
        float esum = 0.f;
        #pragma unroll
        for (int qi = 0; qi < 2; qi++) {
            float a0 = 0.5f * (sp[0][qi][0] + sp[1][qi][0]);
            float a1 = 0.5f * (sp[0][qi][1] + sp[1][qi][1]);
            esum -= a0 * logf(a0 + 1e-9f) + a1 * logf(a1 + 1e-9f);
        }
        ent[t] = esum;
    }
    for (int i = tid; i < 2 * 768; i += 256) {
        int qi = i / 768, c = i - qi * 768;
        int h = c / 384;
        float p0 = sp[h][qi][0], p1 = sp[h][qi][1];
        float v0 = base[1536 + c];           // kj=0 value row
        float v1 = base[2304 + 1536 + c];    // kj=1 value row
        O[(size_t)(t * 2 + qi) * 768 + c] = fmaf(p0, v0, p1 * v1);
    }
}

// ---------------- weighted combine of refined expert streams ----------------
__global__ void combine_kernel(const float* __restrict__ ref, const float* __restrict__ tkp,
                               float* __restrict__ comb)
{
    const int total = TT * DD;
    for (int idx = blockIdx.x * blockDim.x + threadIdx.x; idx < total; idx += gridDim.x * blockDim.x) {
        int t = idx / DD, d = idx - t * DD;
        float p0 = tkp[t * 2], p1 = tkp[t * 2 + 1];
        comb[idx] = fmaf(p0, ref[(size_t)(t * 2) * DD + d], p1 * ref[(size_t)(t * 2 + 1) * DD + d]);
    }
}

// ---------------- aux loss ----------------
__global__ void __launch_bounds__(256) aux_kernel(
    const float* __restrict__ rprobs, const float* __restrict__ ent, float* __restrict__ outp)
{
    const int tid = threadIdx.x;
    __shared__ float red[256];
    float us[8] = {0.f};
    for (int t = tid; t < TT; t += 256)
        #pragma unroll
        for (int e = 0; e < 8; e++) us[e] += rprobs[t * 8 + e];
    float usage[8];
    for (int e = 0; e < 8; e++) {
        red[tid] = us[e]; __syncthreads();
        for (int o = 128; o > 0; o >>= 1) { if (tid < o) red[tid] += red[tid + o]; __syncthreads(); }
        usage[e] = red[0] / (float)TT; __syncthreads();
    }
    float es = 0.f;
    for (int t = tid; t < TT; t += 256) es += ent[t];
    red[tid] = es; __syncthreads();
    for (int o = 128; o > 0; o >>= 1) { if (tid < o) red[tid] += red[tid + o]; __syncthreads(); }
    if (tid == 0) {
        float um = 0.f;
        #pragma unroll
        for (int e = 0; e < 8; e++) um += usage[e];
        um *= 0.125f;
        float bal = 0.f;
        #pragma unroll
        for (int e = 0; e < 8; e++) { float d = usage[e] - um; bal = fmaf(d, d, bal); }
        bal *= 0.125f;
        float div = red[0] / (float)(TT * KX);
        outp[0] = 0.1f * (0.01f * div + 0.01f * bal);
    }
}

// ---------------- host launch ----------------
extern "C" void kernel_launch(void* const* d_in, const int* in_sizes, int n_in,
                              void* d_out, int out_size)
{
    const float* x       = (const float*)d_in[0];
    const float* w1      = (const float*)d_in[1];
    const float* w3      = (const float*)d_in[2];
    const float* w2      = (const float*)d_in[3];
    const float* r_in_w  = (const float*)d_in[4];
    const float* r_in_b  = (const float*)d_in[5];
    const float* r_out_w = (const float*)d_in[6];
    const float* r_out_b = (const float*)d_in[7];
    const float* r_norm  = (const float*)d_in[8];
    const float* gate_w  = (const float*)d_in[9];
    const float* c_in_w  = (const float*)d_in[10];
    const float* c_in_b  = (const float*)d_in[11];
    const float* c_out_w = (const float*)d_in[12];
    const float* c_out_b = (const float*)d_in[13];
    const float* c_norm  = (const float*)d_in[14];
    const float* ffn_w1  = (const float*)d_in[15];
    const float* ffn_w2  = (const float*)d_in[16];
    const float* o_w     = (const float*)d_in[17];
    float* out = (float*)d_out;

    float *act, *eo, *qkv, *attn, *proj, *ctx, *rprobs, *tkp, *sf, *ao, *h1, *ref, *comb, *ent;
    int* tkidx;
    cudaGetSymbolAddress((void**)&act,   g_act);
    cudaGetSymbolAddress((void**)&eo,    g_eo);
    cudaGetSymbolAddress((void**)&qkv,   g_qkv);
    cudaGetSymbolAddress((void**)&attn,  g_attn);
    cudaGetSymbolAddress((void**)&proj,  g_proj);
    cudaGetSymbolAddress((void**)&ctx,   g_ctx);
    cudaGetSymbolAddress((void**)&rprobs,g_rprobs);
    cudaGetSymbolAddress((void**)&tkidx, g_tkidx);
    cudaGetSymbolAddress((void**)&tkp,   g_tkp);
    cudaGetSymbolAddress((void**)&sf,    g_sf);
    cudaGetSymbolAddress((void**)&ao,    g_ao);
    cudaGetSymbolAddress((void**)&h1,    g_h1);
    cudaGetSymbolAddress((void**)&ref,   g_ref);
    cudaGetSymbolAddress((void**)&comb,  g_comb);
    cudaGetSymbolAddress((void**)&ent,   g_ent);

    const bool write_idx = out_size >= (TT * DD + 1 + TT * KX);
    const bool write_aux = out_size >= (TT * DD + 1);

    // 1) SwiGLU: act[e,t,h] = silu(x@w1[e]) * (x@w3[e])
    swiglu_kernel<<<dim3(HH / 64, TT / 64, EE), 256>>>(x, w1, w3, act);
    // 2) expert down-proj: eo[t,e,:] = act_e @ w2[e]
    gemm_kernel<false><<<dim3(DD / 64, TT / 64, EE), 256>>>(
        act, HH, (size_t)TT * HH, w2, DD, (size_t)HH * DD,
        nullptr, nullptr, eo, EE * DD, (size_t)DD, TT, DD, HH, 0);
    // 3) router qkv
    gemm_kernel<true><<<dim3(3 * DD / 64, TT * EE / 64, 1), 256>>>(
        eo, DD, 0, r_in_w, DD, 0, r_in_b, nullptr, qkv, 3 * DD, 0, TT * EE, 3 * DD, DD, 0);
    // 4) router attention (L=8, 12 heads)
    router_attn_kernel<<<TT, 96>>>(qkv, attn);
    // 5) router out-proj
    gemm_kernel<true><<<dim3(DD / 64, TT * EE / 64, 1), 256>>>(
        attn, DD, 0, r_out_w, DD, 0, r_out_b, nullptr, proj, DD, 0, TT * EE, DD, DD, 0);
    // 6) residual + RMS
    rms_kernel<<<TT * EE, 256>>>(proj, eo, r_norm, ctx);
    // 7) logits / routing softmax / top-2
    logits_kernel<<<TT, 256>>>(ctx, gate_w, rprobs, tkidx, tkp,
                               write_idx ? out + (size_t)TT * DD + 1 : nullptr);
    // 8) gather selected experts
    gather_kernel<<<4096, 256>>>(eo, tkidx, sf);
    // 9) collab qkv
    gemm_kernel<true><<<dim3(3 * DD / 64, TT * KX / 64, 1), 256>>>(
        sf, DD, 0, c_in_w, DD, 0, c_in_b, nullptr, qkv, 3 * DD, 0, TT * KX, 3 * DD, DD, 0);
    // 10) collab attention (L=2, 2 heads) + entropy
    collab_attn_kernel<<<TT, 256>>>(qkv, attn, ent);
    // 11) collab out-proj
    gemm_kernel<true><<<dim3(DD / 64, TT * KX / 64, 1), 256>>>(
        attn, DD, 0, c_out_w, DD, 0, c_out_b, nullptr, proj, DD, 0, TT * KX, DD, DD, 0);
    // 12) residual + RMS
    rms_kernel<<<TT * KX, 256>>>(proj, sf, c_norm, ao);
    // 13) FFN up with exact GELU
    gemm_kernel<true><<<dim3(DD / 64, TT * KX / 64, 1), 256>>>(
        ao, DD, 0, ffn_w1, DD, 0, nullptr, nullptr, h1, DD, 0, TT * KX, DD, DD, 1);
    // 14) FFN down + residual(ao)
    gemm_kernel<true><<<dim3(DD / 64, TT * KX / 64, 1), 256>>>(
        h1, DD, 0, ffn_w2, DD, 0, nullptr, ao, ref, DD, 0, TT * KX, DD, DD, 0);
    // 15) weighted combine with top-k probs
    combine_kernel<<<2048, 256>>>(ref, tkp, comb);
    // 16) output projection -> d_out
    gemm_kernel<true><<<dim3(DD / 64, TT / 64, 1), 256>>>(
        comb, DD, 0, o_w, DD, 0, nullptr, nullptr, out, DD, 0, TT, DD, DD, 0);
    // 17) aux loss
    if (write_aux)
        aux_kernel<<<1, 256>>>(rprobs, ent, out + (size_t)TT * DD);
}

// round 2
// speedup vs baseline: 1.1728x; 1.1728x over previous
#include <cuda_runtime.h>
#include <math.h>
#include <stdint.h>

#define TT 4096      // B*S tokens
#define DD 768       // model dim
#define EE 8         // experts
#define KX 2         // top-k
#define HH 2048      // expert hidden

typedef unsigned long long u64;

// ---------------- scratch (device globals) ----------------
__device__ float g_gate[(size_t)EE*TT*HH];
__device__ float g_up  [(size_t)EE*TT*HH];
__device__ float g_act [(size_t)EE*TT*HH];
__device__ float g_eo  [(size_t)TT*EE*DD];
__device__ float g_qkv [(size_t)TT*EE*3*DD];
__device__ float g_attn[(size_t)TT*EE*DD];
__device__ float g_proj[(size_t)TT*EE*DD];
__device__ float g_ctx [(size_t)TT*EE*DD];
__device__ float g_rprobs[TT*EE];
__device__ int   g_tkidx[TT*KX];
__device__ float g_tkp  [TT*KX];
__device__ float g_sf [(size_t)TT*KX*DD];
__device__ float g_ao [(size_t)TT*KX*DD];
__device__ float g_h1 [(size_t)TT*KX*DD];
__device__ float g_ref[(size_t)TT*KX*DD];
__device__ float g_comb[(size_t)TT*DD];
__device__ float g_ent[TT];

// ---------------- packed f32x2 helpers ----------------
__device__ __forceinline__ void ffma2(u64& d, u64 a, u64 b) {
    asm("fma.rn.f32x2 %0, %1, %2, %0;" : "+l"(d) : "l"(a), "l"(b));
}
__device__ __forceinline__ u64 swap64(u64 x) {
    unsigned lo, hi;
    asm("mov.b64 {%0,%1}, %2;" : "=r"(lo), "=r"(hi) : "l"(x));
    u64 r;
    asm("mov.b64 %0, {%1,%2};" : "=l"(r) : "r"(hi), "r"(lo));
    return r;
}
__device__ __forceinline__ float2 unpk(u64 x) {
    float2 f;
    asm("mov.b64 {%0,%1}, %2;" : "=f"(f.x), "=f"(f.y) : "l"(x));
    return f;
}

// ---------------- FFMA2 SGEMM: C = A * op(B) (+bias)(+gelu)(+resid) ----------------
// 128x128 tile, BK=16, 256 threads, 8x8 microtile, double-buffered smem.
// BT=true: B is N x Kd row-major (use B^T). BT=false: B is Kd x N row-major.
// Requires M%128==0, N%128==0, Kd%16==0.
template<bool BT>
__global__ void __launch_bounds__(256) gemm2(
    const float* __restrict__ A, int lda, size_t sA,
    const float* __restrict__ B, int ldb, size_t sB,
    const float* __restrict__ bias,
    const float* __restrict__ resid,
    float* __restrict__ C, int ldc, size_t sC,
    int M, int N, int Kd, int epi)   // epi: 0 none, 1 exact GELU
{
    __shared__ __align__(16) float As[2][16][132];
    __shared__ __align__(16) float Bs[2][16][132];
    const int tid = threadIdx.x;
    A += sA * blockIdx.z; B += sB * blockIdx.z; C += sC * blockIdx.z;
    const int rowBase = blockIdx.y * 128;
    const int colBase = blockIdx.x * 128;

    // A global->smem mapping: thread loads 8 consecutive k at one row
    const int mA = tid >> 1, kA = (tid & 1) << 3;
    const float* Ap = A + (size_t)(rowBase + mA) * lda + kA;
    // B mapping
    int nB, kB;
    const float* Bp;
    if (BT) { nB = tid >> 1; kB = (tid & 1) << 3;
              Bp = B + (size_t)(colBase + nB) * ldb + kB; }
    else    { kB = tid >> 4; nB = (tid & 15) << 3;
              Bp = B + (size_t)kB * ldb + colBase + nB; }

    const int ty = tid >> 4, tx = tid & 15;

    u64 aD[4][4], aX[4][4];
    #pragma unroll
    for (int p = 0; p < 4; p++)
        #pragma unroll
        for (int q = 0; q < 4; q++) { aD[p][q] = 0ull; aX[p][q] = 0ull; }

    float4 ra0, ra1, rb0, rb1;
    auto loadG = [&](int k0) {
        ra0 = *(const float4*)(Ap + k0);
        ra1 = *(const float4*)(Ap + k0 + 4);
        if (BT) {
            rb0 = *(const float4*)(Bp + k0);
            rb1 = *(const float4*)(Bp + k0 + 4);
        } else {
            const float* q = Bp + (size_t)k0 * ldb;
            rb0 = *(const float4*)q;
            rb1 = *(const float4*)(q + 4);
        }
    };
    auto storeS = [&](int buf) {
        As[buf][kA + 0][mA] = ra0.x; As[buf][kA + 1][mA] = ra0.y;
        As[buf][kA + 2][mA] = ra0.z; As[buf][kA + 3][mA] = ra0.w;
        As[buf][kA + 4][mA] = ra1.x; As[buf][kA + 5][mA] = ra1.y;
        As[buf][kA + 6][mA] = ra1.z; As[buf][kA + 7][mA] = ra1.w;
        if (BT) {
            Bs[buf][kB + 0][nB] = rb0.x; Bs[buf][kB + 1][nB] = rb0.y;
            Bs[buf][kB + 2][nB] = rb0.z; Bs[buf][kB + 3][nB] = rb0.w;
            Bs[buf][kB + 4][nB] = rb1.x; Bs[buf][kB + 5][nB] = rb1.y;
            Bs[buf][kB + 6][nB] = rb1.z; Bs[buf][kB + 7][nB] = rb1.w;
        } else {
            *(float4*)&Bs[buf][kB][nB]     = rb0;
            *(float4*)&Bs[buf][kB][nB + 4] = rb1;
        }
    };

    loadG(0);
    storeS(0);
    __syncthreads();

    const int nb = Kd >> 4;
    for (int kb = 0; kb < nb; kb++) {
        const int cur = kb & 1;
        if (kb + 1 < nb) loadG((kb + 1) << 4);
        #pragma unroll
        for (int kk = 0; kk < 16; kk++) {
            const float* Ab = &As[cur][kk][ty << 3];
            ulonglong2 a01 = *(const ulonglong2*)Ab;
            ulonglong2 a23 = *(const ulonglong2*)(Ab + 4);
            u64 ap[4] = {a01.x, a01.y, a23.x, a23.y};
            const float* Bb = &Bs[cur][kk][tx << 3];
            ulonglong2 b01 = *(const ulonglong2*)Bb;
            ulonglong2 b23 = *(const ulonglong2*)(Bb + 4);
            u64 bp[4] = {b01.x, b01.y, b23.x, b23.y};
            u64 bw[4];
            #pragma unroll
            for (int q = 0; q < 4; q++) bw[q] = swap64(bp[q]);
            #pragma unroll
            for (int p = 0; p < 4; p++)
                #pragma unroll
                for (int q = 0; q < 4; q++) {
                    ffma2(aD[p][q], ap[p], bp[q]);
                    ffma2(aX[p][q], ap[p], bw[q]);
                }
        }
        if (kb + 1 < nb) storeS(cur ^ 1);
        __syncthreads();
    }

    // unscramble diagonal packing
    float c[8][8];
    #pragma unroll
    for (int p = 0; p < 4; p++)
        #pragma unroll
        for (int q = 0; q < 4; q++) {
            float2 d = unpk(aD[p][q]);
            float2 x = unpk(aX[p][q]);
            c[2*p  ][2*q  ] = d.x; c[2*p+1][2*q+1] = d.y;
            c[2*p  ][2*q+1] = x.x; c[2*p+1][2*q  ] = x.y;
        }

    const int row0 = rowBase + (ty << 3);
    const int col0 = colBase + (tx << 3);
    #pragma unroll
    for (int i = 0; i < 8; i++) {
        int r = row0 + i;
        float4 o0, o1;
        #pragma unroll
        for (int j = 0; j < 8; j++) {
            float v = c[i][j];
            int cc = col0 + j;
            if (bias)  v += __ldg(&bias[cc]);
            if (epi == 1) v = 0.5f * v * (1.0f + erff(v * 0.7071067811865475f));
            if (resid) v += resid[(size_t)r * ldc + cc];
            if (j < 4) (&o0.x)[j] = v; else (&o1.x)[j - 4] = v;
        }
        float* cp = C + (size_t)r * ldc + col0;
        *(float4*)cp       = o0;
        *(float4*)(cp + 4) = o1;
    }
}

// ---------------- elementwise SwiGLU: act = silu(gate) * up ----------------
__global__ void swiglu_mul(const float* __restrict__ g, const float* __restrict__ u,
                           float* __restrict__ a, size_t n4)
{
    for (size_t i = blockIdx.x * blockDim.x + threadIdx.x; i < n4;
         i += (size_t)gridDim.x * blockDim.x) {
        float4 gv = ((const float4*)g)[i];
        float4 uv = ((const float4*)u)[i];
        float4 av;
        av.x = gv.x / (1.0f + expf(-gv.x)) * uv.x;
        av.y = gv.y / (1.0f + expf(-gv.y)) * uv.y;
        av.z = gv.z / (1.0f + expf(-gv.z)) * uv.z;
        av.w = gv.w / (1.0f + expf(-gv.w)) * uv.w;
        ((float4*)a)[i] = av;
    }
}

// ---------------- router self-attention over E=8 positions, 12 heads, hd=64 ----------------
__global__ void __launch_bounds__(96) router_attn_kernel(
    const float* __restrict__ QKV,   // (T*8) x 2304
    float* __restrict__ O)           // (T*8) x 768
{
    __shared__ float sK[8 * 768];
    __shared__ float sV[8 * 768];
    const int t = blockIdx.x;
    const int tid = threadIdx.x;
    const float* base = QKV + (size_t)t * 8 * 2304;
    for (int i = tid; i < 8 * 768; i += 96) {
        int pos = i / 768, c = i - pos * 768;
        sK[i] = base[(size_t)pos * 2304 +  768 + c];
        sV[i] = base[(size_t)pos * 2304 + 1536 + c];
    }
    __syncthreads();
    const int head = tid / 8, qi = tid % 8;
    const float* q = base + (size_t)qi * 2304 + head * 64;
    float s[8] = {0.f};
    for (int d = 0; d < 64; d++) {
        float qd = q[d];
        #pragma unroll
        for (int m = 0; m < 8; m++) s[m] = fmaf(qd, sK[m * 768 + head * 64 + d], s[m]);
    }
    float mx = -1e30f;
    #pragma unroll
    for (int m = 0; m < 8; m++) { s[m] *= 0.125f; mx = fmaxf(mx, s[m]); }
    float den = 0.f;
    #pragma unroll
    for (int m = 0; m < 8; m++) { s[m] = expf(s[m] - mx); den += s[m]; }
    float inv = 1.0f / den;
    #pragma unroll
    for (int m = 0; m < 8; m++) s[m] *= inv;
    float* op = O + (size_t)(t * 8 + qi) * 768 + head * 64;
    for (int d = 0; d < 64; d++) {
        float o = 0.f;
        #pragma unroll
        for (int m = 0; m < 8; m++) o = fmaf(s[m], sV[m * 768 + head * 64 + d], o);
        op[d] = o;
    }
}

// ---------------- RMS-norm with residual ----------------
__global__ void __launch_bounds__(256) rms_kernel(
    const float* __restrict__ Y, const float* __restrict__ R,
    const float* __restrict__ W, float* __restrict__ O)
{
    const int row = blockIdx.x, tid = threadIdx.x;
    const float* y = Y + (size_t)row * 768;
    const float* r = R + (size_t)row * 768;
    float v[3]; float ss = 0.f;
    #pragma unroll
    for (int i = 0; i < 3; i++) {
        int c = tid + i * 256;
        float s = y[c] + r[c];
        v[i] = s; ss = fmaf(s, s, ss);
    }
    __shared__ float red[256];
    red[tid] = ss; __syncthreads();
    for (int o = 128; o > 0; o >>= 1) { if (tid < o) red[tid] += red[tid + o]; __syncthreads(); }
    float scale = rsqrtf(red[0] * (1.0f / 768.0f) + 1e-5f);
    #pragma unroll
    for (int i = 0; i < 3; i++) {
        int c = tid + i * 256;
        O[(size_t)row * 768 + c] = v[i] * scale * W[c];
    }
}

// ---------------- logits, routing softmax, top-2 ----------------
__global__ void __launch_bounds__(256) logits_kernel(
    const float* __restrict__ CTX, const float* __restrict__ GW,
    float* __restrict__ rprobs, int* __restrict__ tkidx,
    float* __restrict__ tkp, float* __restrict__ out_idx_f)
{
    const int t = blockIdx.x, tid = threadIdx.x;
    __shared__ float mv[768];
    const float* c0 = CTX + (size_t)t * 8 * 768;
    for (int i = tid; i < 768; i += 256) {
        float s = 0.f;
        #pragma unroll
        for (int p = 0; p < 8; p++) s += c0[p * 768 + i];
        mv[i] = s * 0.125f;
    }
    __syncthreads();
    const int w = tid >> 5, lane = tid & 31;
    float part = 0.f;
    for (int i = lane; i < 768; i += 32) part = fmaf(mv[i], GW[w * 768 + i], part);
    #pragma unroll
    for (int o = 16; o; o >>= 1) part += __shfl_xor_sync(0xffffffffu, part, o);
    __shared__ float lg[8];
    if (lane == 0) lg[w] = part;
    __syncthreads();
    if (tid == 0) {
        float mx = lg[0];
        #pragma unroll
        for (int e = 1; e < 8; e++) mx = fmaxf(mx, lg[e]);
        float ex[8], den = 0.f;
        #pragma unroll
        for (int e = 0; e < 8; e++) { ex[e] = expf(lg[e] - mx); den += ex[e]; }
        float inv = 1.0f / den;
        #pragma unroll
        for (int e = 0; e < 8; e++) rprobs[t * 8 + e] = ex[e] * inv;
        int i0 = 0;
        #pragma unroll
        for (int e = 1; e < 8; e++) if (lg[e] > lg[i0]) i0 = e;
        int i1 = -1;
        #pragma unroll
        for (int e = 0; e < 8; e++) if (e != i0 && (i1 < 0 || lg[e] > lg[i1])) i1 = e;
        tkidx[t * 2] = i0; tkidx[t * 2 + 1] = i1;
        float eb = expf(lg[i1] - lg[i0]);
        float p0 = 1.0f / (1.0f + eb);
        tkp[t * 2] = p0; tkp[t * 2 + 1] = eb * p0;
        if (out_idx_f) { out_idx_f[t * 2] = (float)i0; out_idx_f[t * 2 + 1] = (float)i1; }
    }
}

// ---------------- gather selected experts ----------------
__global__ void gather_kernel(const float* __restrict__ eo, const int* __restrict__ tkidx,
                              float* __restrict__ sf)
{
    const int total = TT * KX * DD;
    for (int idx = blockIdx.x * blockDim.x + threadIdx.x; idx < total; idx += gridDim.x * blockDim.x) {
        int d = idx % DD;
        int r = idx / DD;
        int t = r >> 1, k = r & 1;
        sf[idx] = eo[(size_t)t * EE * DD + (size_t)tkidx[t * 2 + k] * DD + d];
    }
}

// ---------------- collaborative attention: L=2, 2 heads, hd=384; + entropy ----------------
__global__ void __launch_bounds__(256) collab_attn_kernel(
    const float* __restrict__ QKV, float* __restrict__ O, float* __restrict__ ent)
{
    const int t = blockIdx.x, tid = threadIdx.x;
    const float* base = QKV + (size_t)t * 2 * 2304;
    __shared__ float sc[2][2][2];
    __shared__ float sp[2][2][2];
    const int w = tid >> 5, lane = tid & 31;
    {
        int h = (w >> 2) & 1, qi = (w >> 1) & 1, kj = w & 1;
        float part = 0.f;
        const float* qp = base + (size_t)qi * 2304 + h * 384;
        const float* kp = base + (size_t)kj * 2304 + 768 + h * 384;
        for (int d = lane; d < 384; d += 32) part = fmaf(qp[d], kp[d], part);
        #pragma unroll
        for (int o = 16; o; o >>= 1) part += __shfl_xor_sync(0xffffffffu, part, o);
        if (lane == 0) sc[h][qi][kj] = part * 0.05103103630798288f;
    }
    __syncthreads();
    if (tid < 4) {
        int h = tid >> 1, qi = tid & 1;
        float s0 = sc[h][qi][0], s1 = sc[h][qi][1];
        float m = fmaxf(s0, s1);
        float e0 = expf(s0 - m), e1 = expf(s1 - m);
        float inv = 1.0f / (e0 + e1);
        sp[h][qi][0] = e0 * inv; sp[h][qi][1] = e1 * inv;
    }
    __syncthreads();
    if (tid == 0) {
        float esum = 0.f;
        #pragma unroll
        for (int qi = 0; qi < 2; qi++) {
            float a0 = 0.5f * (sp[0][qi][0] + sp[1][qi][0]);
            float a1 = 0.5f * (sp[0][qi][1] + sp[1][qi][1]);
            esum -= a0 * logf(a0 + 1e-9f) + a1 * logf(a1 + 1e-9f);
        }
        ent[t] = esum;
    }
    for (int i = tid; i < 2 * 768; i += 256) {
        int qi = i / 768, c = i - qi * 768;
        int h = c / 384;
        float p0 = sp[h][qi][0], p1 = sp[h][qi][1];
        float v0 = base[1536 + c];
        float v1 = base[2304 + 1536 + c];
        O[(size_t)(t * 2 + qi) * 768 + c] = fmaf(p0, v0, p1 * v1);
    }
}

// ---------------- weighted combine ----------------
__global__ void combine_kernel(const float* __restrict__ ref, const float* __restrict__ tkp,
                               float* __restrict__ comb)
{
    const int total = TT * DD;
    for (int idx = blockIdx.x * blockDim.x + threadIdx.x; idx < total; idx += gridDim.x * blockDim.x) {
        int t = idx / DD, d = idx - t * DD;
        float p0 = tkp[t * 2], p1 = tkp[t * 2 + 1];
        comb[idx] = fmaf(p0, ref[(size_t)(t * 2) * DD + d], p1 * ref[(size_t)(t * 2 + 1) * DD + d]);
    }
}

// ---------------- aux loss ----------------
__global__ void __launch_bounds__(256) aux_kernel(
    const float* __restrict__ rprobs, const float* __restrict__ ent, float* __restrict__ outp)
{
    const int tid = threadIdx.x;
    __shared__ float red[256];
    float us[8] = {0.f};
    for (int t = tid; t < TT; t += 256)
        #pragma unroll
        for (int e = 0; e < 8; e++) us[e] += rprobs[t * 8 + e];
    float usage[8];
    for (int e = 0; e < 8; e++) {
        red[tid] = us[e]; __syncthreads();
        for (int o = 128; o > 0; o >>= 1) { if (tid < o) red[tid] += red[tid + o]; __syncthreads(); }
        usage[e] = red[0] / (float)TT; __syncthreads();
    }
    float es = 0.f;
    for (int t = tid; t < TT; t += 256) es += ent[t];
    red[tid] = es; __syncthreads();
    for (int o = 128; o > 0; o >>= 1) { if (tid < o) red[tid] += red[tid + o]; __syncthreads(); }
    if (tid == 0) {
        float um = 0.f;
        #pragma unroll
        for (int e = 0; e < 8; e++) um += usage[e];
        um *= 0.125f;
        float bal = 0.f;
        #pragma unroll
        for (int e = 0; e < 8; e++) { float d = usage[e] - um; bal = fmaf(d, d, bal); }
        bal *= 0.125f;
        float div = red[0] / (float)(TT * KX);
        outp[0] = 0.1f * (0.01f * div + 0.01f * bal);
    }
}

// ---------------- host launch ----------------
extern "C" void kernel_launch(void* const* d_in, const int* in_sizes, int n_in,
                              void* d_out, int out_size)
{
    const float* x       = (const float*)d_in[0];
    const float* w1      = (const float*)d_in[1];
    const float* w3      = (const float*)d_in[2];
    const float* w2      = (const float*)d_in[3];
    const float* r_in_w  = (const float*)d_in[4];
    const float* r_in_b  = (const float*)d_in[5];
    const float* r_out_w = (const float*)d_in[6];
    const float* r_out_b = (const float*)d_in[7];
    const float* r_norm  = (const float*)d_in[8];
    const float* gate_w  = (const float*)d_in[9];
    const float* c_in_w  = (const float*)d_in[10];
    const float* c_in_b  = (const float*)d_in[11];
    const float* c_out_w = (const float*)d_in[12];
    const float* c_out_b = (const float*)d_in[13];
    const float* c_norm  = (const float*)d_in[14];
    const float* ffn_w1  = (const float*)d_in[15];
    const float* ffn_w2  = (const float*)d_in[16];
    const float* o_w     = (const float*)d_in[17];
    float* out = (float*)d_out;

    float *gatep, *upp, *act, *eo, *qkv, *attn, *proj, *ctx, *rprobs, *tkp, *sf, *ao, *h1, *ref, *comb, *ent;
    int* tkidx;
    cudaGetSymbolAddress((void**)&gatep, g_gate);
    cudaGetSymbolAddress((void**)&upp,   g_up);
    cudaGetSymbolAddress((void**)&act,   g_act);
    cudaGetSymbolAddress((void**)&eo,    g_eo);
    cudaGetSymbolAddress((void**)&qkv,   g_qkv);
    cudaGetSymbolAddress((void**)&attn,  g_attn);
    cudaGetSymbolAddress((void**)&proj,  g_proj);
    cudaGetSymbolAddress((void**)&ctx,   g_ctx);
    cudaGetSymbolAddress((void**)&rprobs,g_rprobs);
    cudaGetSymbolAddress((void**)&tkidx, g_tkidx);
    cudaGetSymbolAddress((void**)&tkp,   g_tkp);
    cudaGetSymbolAddress((void**)&sf,    g_sf);
    cudaGetSymbolAddress((void**)&ao,    g_ao);
    cudaGetSymbolAddress((void**)&h1,    g_h1);
    cudaGetSymbolAddress((void**)&ref,   g_ref);
    cudaGetSymbolAddress((void**)&comb,  g_comb);
    cudaGetSymbolAddress((void**)&ent,   g_ent);

    const bool write_idx = out_size >= (TT * DD + 1 + TT * KX);
    const bool write_aux = out_size >= (TT * DD + 1);

    // 1) gate = x @ w1[e], up = x @ w3[e]   (NN GEMMs)
    gemm2<false><<<dim3(HH / 128, TT / 128, EE), 256>>>(
        x, DD, 0, w1, HH, (size_t)DD * HH, nullptr, nullptr,
        gatep, HH, (size_t)TT * HH, TT, HH, DD, 0);
    gemm2<false><<<dim3(HH / 128, TT / 128, EE), 256>>>(
        x, DD, 0, w3, HH, (size_t)DD * HH, nullptr, nullptr,
        upp, HH, (size_t)TT * HH, TT, HH, DD, 0);
    // 2) act = silu(gate) * up
    swiglu_mul<<<8192, 256>>>(gatep, upp, act, (size_t)EE * TT * HH / 4);
    // 3) expert down-proj: eo[t,e,:] = act_e @ w2[e]
    gemm2<false><<<dim3(DD / 128, TT / 128, EE), 256>>>(
        act, HH, (size_t)TT * HH, w2, DD, (size_t)HH * DD, nullptr, nullptr,
        eo, EE * DD, (size_t)DD, TT, DD, HH, 0);
    // 4) router qkv
    gemm2<true><<<dim3(3 * DD / 128, TT * EE / 128, 1), 256>>>(
        eo, DD, 0, r_in_w, DD, 0, r_in_b, nullptr, qkv, 3 * DD, 0, TT * EE, 3 * DD, DD, 0);
    // 5) router attention
    router_attn_kernel<<<TT, 96>>>(qkv, attn);
    // 6) router out-proj
    gemm2<true><<<dim3(DD / 128, TT * EE / 128, 1), 256>>>(
        attn, DD, 0, r_out_w, DD, 0, r_out_b, nullptr, proj, DD, 0, TT * EE, DD, DD, 0);
    // 7) residual + RMS
    rms_kernel<<<TT * EE, 256>>>(proj, eo, r_norm, ctx);
    // 8) logits / routing softmax / top-2
    logits_kernel<<<TT, 256>>>(ctx, gate_w, rprobs, tkidx, tkp,
                               write_idx ? out + (size_t)TT * DD + 1 : nullptr);
    // 9) gather selected experts
    gather_kernel<<<4096, 256>>>(eo, tkidx, sf);
    // 10) collab qkv
    gemm2<true><<<dim3(3 * DD / 128, TT * KX / 128, 1), 256>>>(
        sf, DD, 0, c_in_w, DD, 0, c_in_b, nullptr, qkv, 3 * DD, 0, TT * KX, 3 * DD, DD, 0);
    // 11) collab attention + entropy
    collab_attn_kernel<<<TT, 256>>>(qkv, attn, ent);
    // 12) collab out-proj
    gemm2<true><<<dim3(DD / 128, TT * KX / 128, 1), 256>>>(
        attn, DD, 0, c_out_w, DD, 0, c_out_b, nullptr, proj, DD, 0, TT * KX, DD, DD, 0);
    // 13) residual + RMS
    rms_kernel<<<TT * KX, 256>>>(proj, sf, c_norm, ao);
    // 14) FFN up with exact GELU
    gemm2<true><<<dim3(DD / 128, TT * KX / 128, 1), 256>>>(
        ao, DD, 0, ffn_w1, DD, 0, nullptr, nullptr, h1, DD, 0, TT * KX, DD, DD, 1);
    // 15) FFN down + residual(ao)
    gemm2<true><<<dim3(DD / 128, TT * KX / 128, 1), 256>>>(
        h1, DD, 0, ffn_w2, DD, 0, nullptr, ao, ref, DD, 0, TT * KX, DD, DD, 0);
    // 16) weighted combine
    combine_kernel<<<2048, 256>>>(ref, tkp, comb);
    // 17) output projection -> d_out
    gemm2<true><<<dim3(DD / 128, TT / 128, 1), 256>>>(
        comb, DD, 0, o_w, DD, 0, nullptr, nullptr, out, DD, 0, TT, DD, DD, 0);
    // 18) aux loss
    if (write_aux)
        aux_kernel<<<1, 256>>>(rprobs, ent, out + (size_t)TT * DD);
}